// round 14
// baseline (speedup 1.0000x reference)
#include <cuda_runtime.h>
#include <cuda_fp16.h>
#include <cstdint>

#define NN 50000
#define EE 800000

// ---------------- scratch (static device globals; no allocs) ----------------
__device__ __half g_m2[NN * 128];
__device__ float g_qp1[NN * 256];   // [node][0:128]=q1, [128:256]=p1
__device__ float g_qp2[NN * 128];   // [node][0:64]=q2, [64:128]=p2
__device__ __half g_wqp2c[128 * 128];   // [k][n]: n<64 -> Wq2, else Wp2
__device__ int   g_rowptr[NN + 1];
__device__ int   g_cursor[NN];
__device__ int   g_esrc[EE];

__device__ __forceinline__ float gelu_f(float x) {
    return 0.5f * x * (1.0f + erff(x * 0.70710678118654752440f));
}
__device__ __forceinline__ uint32_t smem_u32(const void* p) {
    uint32_t a;
    asm("{ .reg .u64 t; cvta.to.shared.u64 t, %1; cvt.u32.u64 %0, t; }" : "=r"(a) : "l"(p));
    return a;
}
__device__ __forceinline__ void ldsm4(uint32_t& r0, uint32_t& r1, uint32_t& r2, uint32_t& r3, uint32_t addr) {
    asm volatile("ldmatrix.sync.aligned.m8n8.x4.shared.b16 {%0,%1,%2,%3}, [%4];"
                 : "=r"(r0), "=r"(r1), "=r"(r2), "=r"(r3) : "r"(addr));
}
__device__ __forceinline__ void ldsm4t(uint32_t& r0, uint32_t& r1, uint32_t& r2, uint32_t& r3, uint32_t addr) {
    asm volatile("ldmatrix.sync.aligned.m8n8.x4.trans.shared.b16 {%0,%1,%2,%3}, [%4];"
                 : "=r"(r0), "=r"(r1), "=r"(r2), "=r"(r3) : "r"(addr));
}
__device__ __forceinline__ void mma_f16(float* c, const uint32_t* a, const uint32_t* b) {
    asm volatile(
        "mma.sync.aligned.m16n8k16.row.col.f32.f16.f16.f32 "
        "{%0,%1,%2,%3}, {%4,%5,%6,%7}, {%8,%9}, {%0,%1,%2,%3};"
        : "+f"(c[0]), "+f"(c[1]), "+f"(c[2]), "+f"(c[3])
        : "r"(a[0]), "r"(a[1]), "r"(a[2]), "r"(a[3]), "r"(b[0]), "r"(b[1]));
}
__device__ __forceinline__ void cp16(uint32_t saddr, const void* gaddr) {
    asm volatile("cp.async.cg.shared.global [%0], [%1], 16;" :: "r"(saddr), "l"(gaddr) : "memory");
}

#define ASTRIDE 136
#define ABUF (128 * ASTRIDE * 2)   // 34816 B per buffer

// single-term fp16 mainloop; B stored [k][n] in smem, fragments via ldmatrix.trans
__device__ __forceinline__ void mainloop_1t(
    uint32_t ah_base, uint32_t bh_base,
    int wm, int wn, int lane, float acc[2][8][4])
{
    const int a_r = (lane & 15);
    const int a_c = (lane >> 4) * 8;
    const int b_r = (lane & 15);          // k row within 16
    const int b_c = (lane >> 4) * 8;      // n offset within 16-group
#pragma unroll
    for (int ks = 0; ks < 8; ks++) {
        const int k0 = ks * 16;
        uint32_t ah[2][4];
#pragma unroll
        for (int mt = 0; mt < 2; mt++) {
            uint32_t off = (uint32_t)((wm * 32 + mt * 16 + a_r) * ASTRIDE + k0 + a_c) * 2;
            ldsm4(ah[mt][0], ah[mt][1], ah[mt][2], ah[mt][3], ah_base + off);
        }
        uint32_t bh[8][2];
#pragma unroll
        for (int ng = 0; ng < 4; ng++) {
            uint32_t off = (uint32_t)((k0 + b_r) * ASTRIDE + wn * 64 + ng * 16 + b_c) * 2;
            ldsm4t(bh[2 * ng][0], bh[2 * ng][1], bh[2 * ng + 1][0], bh[2 * ng + 1][1], bh_base + off);
        }
#pragma unroll
        for (int mt = 0; mt < 2; mt++)
#pragma unroll
            for (int nt = 0; nt < 8; nt++)
                mma_f16(acc[mt][nt], ah[mt], bh[nt]);
    }
}

// ---------------- CSR build ----------------
__global__ void zero_k() {
    int i = blockIdx.x * blockDim.x + threadIdx.x;
    if (i < NN) g_cursor[i] = 0;
}
__global__ void hist_k(const int* __restrict__ dst) {
    int e = blockIdx.x * blockDim.x + threadIdx.x;
    if (e < EE) atomicAdd(&g_cursor[dst[e]], 1);
}
__global__ __launch_bounds__(1024) void scan_k() {
    __shared__ int warpsum[32];
    __shared__ int s_carry;
    __shared__ int s_tot;
    int tid = threadIdx.x, lane = tid & 31, wid = tid >> 5;
    if (tid == 0) s_carry = 0;
    __syncthreads();
    for (int base = 0; base < NN; base += 8192) {
        int idx0 = base + tid * 8;
        int v[8]; int tot = 0;
#pragma unroll
        for (int j = 0; j < 8; j++) {
            int id = idx0 + j;
            v[j] = (id < NN) ? g_cursor[id] : 0;
            tot += v[j];
        }
        int incl = tot;
#pragma unroll
        for (int off = 1; off < 32; off <<= 1) {
            int t = __shfl_up_sync(0xffffffffu, incl, off);
            if (lane >= off) incl += t;
        }
        if (lane == 31) warpsum[wid] = incl;
        __syncthreads();
        if (wid == 0) {
            int w = warpsum[lane];
            int wi = w;
#pragma unroll
            for (int off = 1; off < 32; off <<= 1) {
                int t = __shfl_up_sync(0xffffffffu, wi, off);
                if (lane >= off) wi += t;
            }
            warpsum[lane] = wi - w;
            if (lane == 31) s_tot = wi;
        }
        __syncthreads();
        int run = s_carry + warpsum[wid] + (incl - tot);
#pragma unroll
        for (int j = 0; j < 8; j++) {
            int id = idx0 + j;
            if (id < NN) { g_rowptr[id] = run; g_cursor[id] = 0; }
            run += v[j];
        }
        __syncthreads();
        if (tid == 0) s_carry += s_tot;
        __syncthreads();
    }
    if (threadIdx.x == 0) g_rowptr[NN] = s_carry;
}
__global__ void scatter_k(const int* __restrict__ src, const int* __restrict__ dst) {
    int e = blockIdx.x * blockDim.x + threadIdx.x;
    if (e < EE) {
        int d = dst[e];
        int pos = g_rowptr[d] + atomicAdd(&g_cursor[d], 1);
        g_esrc[pos] = src[e];
    }
}

// ---------------- layer-2 weight merge+convert (side stream; no transpose) ---
__global__ void convw2_k(const float* __restrict__ Wq2, const float* __restrict__ Wp2) {
    int i = blockIdx.x * blockDim.x + threadIdx.x;
    if (i < 128 * 128) {
        int k = i >> 7, n = i & 127;
        float v = (n < 64) ? Wq2[(size_t)k * 64 + n] : Wp2[(size_t)k * 64 + (n - 64)];
        g_wqp2c[i] = __float2half_rn(v);
    }
}

// ---------------- fused layer-1: qp1 = gelu(x@W0+b0) @ [Wq1|Wp1] + [bq1|bp1] --
// All operands converted fp32->fp16 in-register at staging; no pre-conversion.
__global__ __launch_bounds__(256, 2) void gemm_l1(
    const float* __restrict__ x, const float* __restrict__ W0,
    const float* __restrict__ b0,
    const float* __restrict__ Wq1, const float* __restrict__ bq1,
    const float* __restrict__ Wp1, const float* __restrict__ bp1,
    float* __restrict__ qp1, int M)
{
    extern __shared__ char sm[];
    char* AH = sm;
    char* BH = sm + ABUF;

    const int tid = threadIdx.x;
    const int warp = tid >> 5, lane = tid & 31;
    const int wm = warp >> 1, wn = warp & 1;
    const int rowBase = blockIdx.x * 128;

    const uint32_t ah_base = smem_u32(AH);
    const uint32_t bh_base = smem_u32(BH);

    // ---- stage W0 [k][n] + x, both fp32 -> fp16 in regs ----
#pragma unroll
    for (int it = 0; it < 8; it++) {
        int idx = tid + it * 256;               // 0..2047
        int row = idx >> 4, ch = idx & 15;      // row = k for W0
        float4 v0 = *(const float4*)(W0 + (size_t)row * 128 + ch * 8);
        float4 v1 = *(const float4*)(W0 + (size_t)row * 128 + ch * 8 + 4);
        __half hh[8];
        hh[0] = __float2half_rn(v0.x); hh[1] = __float2half_rn(v0.y);
        hh[2] = __float2half_rn(v0.z); hh[3] = __float2half_rn(v0.w);
        hh[4] = __float2half_rn(v1.x); hh[5] = __float2half_rn(v1.y);
        hh[6] = __float2half_rn(v1.z); hh[7] = __float2half_rn(v1.w);
        uint32_t so = (uint32_t)(row * ASTRIDE + ch * 8) * 2;
        *(uint4*)(BH + so) = *(const uint4*)hh;
    }
#pragma unroll
    for (int it = 0; it < 8; it++) {
        int idx = tid + it * 256;
        int row = idx >> 4, ch = idx & 15;
        int gr = rowBase + row; if (gr >= M) gr = M - 1;
        float4 v0 = *(const float4*)(x + (size_t)gr * 128 + ch * 8);
        float4 v1 = *(const float4*)(x + (size_t)gr * 128 + ch * 8 + 4);
        __half hh[8];
        hh[0] = __float2half_rn(v0.x); hh[1] = __float2half_rn(v0.y);
        hh[2] = __float2half_rn(v0.z); hh[3] = __float2half_rn(v0.w);
        hh[4] = __float2half_rn(v1.x); hh[5] = __float2half_rn(v1.y);
        hh[6] = __float2half_rn(v1.z); hh[7] = __float2half_rn(v1.w);
        uint32_t so = (uint32_t)(row * ASTRIDE + ch * 8) * 2;
        *(uint4*)(AH + so) = *(const uint4*)hh;
    }
    __syncthreads();

    float acc[2][8][4];
#pragma unroll
    for (int i = 0; i < 2; i++)
#pragma unroll
        for (int j = 0; j < 8; j++)
#pragma unroll
            for (int k = 0; k < 4; k++) acc[i][j][k] = 0.f;

    // ---- mainloop 1: m1 = x @ W0 ----
    mainloop_1t(ah_base, bh_base, wm, wn, lane, acc);
    __syncthreads();   // everyone done reading AH

    // ---- epilogue 1: gelu(m1+b0) -> fp16 back into AH ----
#pragma unroll
    for (int mt = 0; mt < 2; mt++)
#pragma unroll
        for (int nt = 0; nt < 8; nt++) {
            int c = wn * 64 + nt * 8 + (lane & 3) * 2;
            float bb0 = b0[c], bb1 = b0[c + 1];
#pragma unroll
            for (int h = 0; h < 2; h++) {
                int r = wm * 32 + mt * 16 + (lane >> 2) + h * 8;
                float v0 = gelu_f(acc[mt][nt][2 * h + 0] + bb0);
                float v1 = gelu_f(acc[mt][nt][2 * h + 1] + bb1);
                uint32_t so = (uint32_t)(r * ASTRIDE + c) * 2;
                __half2 hh;
                hh.x = __float2half_rn(v0);
                hh.y = __float2half_rn(v1);
                *(__half2*)(AH + so) = hh;
            }
        }
    __syncthreads();

    // ---- stage 2: qp1 halves; W tiles from Wq1 (cb=0) / Wp1 (cb=1) ----
#pragma unroll
    for (int cb = 0; cb < 2; cb++) {
        const float* Wsrc = cb ? Wp1 : Wq1;
        const float* bsrc = cb ? bp1 : bq1;
#pragma unroll
        for (int it = 0; it < 8; it++) {
            int idx = tid + it * 256;
            int row = idx >> 4, ch = idx & 15;   // row = k
            float4 v0 = *(const float4*)(Wsrc + (size_t)row * 128 + ch * 8);
            float4 v1 = *(const float4*)(Wsrc + (size_t)row * 128 + ch * 8 + 4);
            __half hh[8];
            hh[0] = __float2half_rn(v0.x); hh[1] = __float2half_rn(v0.y);
            hh[2] = __float2half_rn(v0.z); hh[3] = __float2half_rn(v0.w);
            hh[4] = __float2half_rn(v1.x); hh[5] = __float2half_rn(v1.y);
            hh[6] = __float2half_rn(v1.z); hh[7] = __float2half_rn(v1.w);
            uint32_t so = (uint32_t)(row * ASTRIDE + ch * 8) * 2;
            *(uint4*)(BH + so) = *(const uint4*)hh;
        }
        __syncthreads();

#pragma unroll
        for (int i = 0; i < 2; i++)
#pragma unroll
            for (int j = 0; j < 8; j++)
#pragma unroll
                for (int k = 0; k < 4; k++) acc[i][j][k] = 0.f;
        mainloop_1t(ah_base, bh_base, wm, wn, lane, acc);

#pragma unroll
        for (int mt = 0; mt < 2; mt++)
#pragma unroll
            for (int nt = 0; nt < 8; nt++) {
                int cl = wn * 64 + nt * 8 + (lane & 3) * 2;
                int c = cb * 128 + cl;
                float bb0 = bsrc[cl], bb1 = bsrc[cl + 1];
#pragma unroll
                for (int h = 0; h < 2; h++) {
                    int r = rowBase + wm * 32 + mt * 16 + (lane >> 2) + h * 8;
                    if (r < M) {
                        float v0 = acc[mt][nt][2 * h + 0] + bb0;
                        float v1 = acc[mt][nt][2 * h + 1] + bb1;
                        *(float2*)(qp1 + (size_t)r * 256 + c) = make_float2(v0, v1);
                    }
                }
            }
        if (cb == 0) __syncthreads();   // before overwriting BH
    }
}

// ---------------- layer-2 GEMM: qp2 = m2(fp16) @ wqp2c + [bq2|bp2] -----------
__global__ __launch_bounds__(256, 2) void gemm_mma(
    const __half* __restrict__ A, const __half* __restrict__ Bh,
    const float* __restrict__ bq2, const float* __restrict__ bp2,
    float* __restrict__ Cf, int M)
{
    extern __shared__ char sm[];
    char* AH = sm;
    char* BH = sm + ABUF;

    const int tid = threadIdx.x;
    const int warp = tid >> 5, lane = tid & 31;
    const int wm = warp >> 1, wn = warp & 1;
    const int rowBase = blockIdx.x * 128;

    const uint32_t ah_base = smem_u32(AH);
    const uint32_t bh_base = smem_u32(BH);

#pragma unroll
    for (int it = 0; it < 8; it++) {
        int idx = tid + it * 256;
        int row = idx >> 4, ch = idx & 15;
        int gr = rowBase + row; if (gr >= M) gr = M - 1;
        uint32_t so = (uint32_t)(row * ASTRIDE + ch * 8) * 2;
        cp16(ah_base + so, A + (size_t)gr * 128 + ch * 8);
        cp16(bh_base + so, Bh + (size_t)row * 128 + ch * 8);   // row = k
    }
    asm volatile("cp.async.commit_group;" ::: "memory");
    asm volatile("cp.async.wait_group 0;" ::: "memory");
    __syncthreads();

    float acc[2][8][4];
#pragma unroll
    for (int i = 0; i < 2; i++)
#pragma unroll
        for (int j = 0; j < 8; j++)
#pragma unroll
            for (int k = 0; k < 4; k++) acc[i][j][k] = 0.f;
    mainloop_1t(ah_base, bh_base, wm, wn, lane, acc);

#pragma unroll
    for (int mt = 0; mt < 2; mt++)
#pragma unroll
        for (int nt = 0; nt < 8; nt++) {
            int c = wn * 64 + nt * 8 + (lane & 3) * 2;
            float b0 = (c < 64) ? bq2[c] : bp2[c - 64];
            float b1 = (c + 1 < 64) ? bq2[c + 1] : bp2[c + 1 - 64];
#pragma unroll
            for (int h = 0; h < 2; h++) {
                int r = rowBase + wm * 32 + mt * 16 + (lane >> 2) + h * 8;
                if (r < M) {
                    float v0 = acc[mt][nt][2 * h + 0] + b0;
                    float v1 = acc[mt][nt][2 * h + 1] + b1;
                    *(float2*)(Cf + (size_t)r * 128 + c) = make_float2(v0, v1);
                }
            }
        }
}

// ---------------- edge kernels: one warp per dst node (R8 formulation) --------
__global__ __launch_bounds__(256) void edge128_k(
    const float* __restrict__ qp, const float* __restrict__ a,
    const float* __restrict__ bg)
{
    int gw = (blockIdx.x * 256 + threadIdx.x) >> 5;
    if (gw >= NN) return;
    int lane = threadIdx.x & 31;
    int c = lane * 4;
    float4 qv = *(const float4*)(qp + (size_t)gw * 256 + c);
    float4 av = *(const float4*)(a + c);
    float ax = 0.f, ay = 0.f, az = 0.f, aw = 0.f;
    float denom = 0.f;
    int i = g_rowptr[gw];
    int end = g_rowptr[gw + 1];
    if (i < end) {
        int s = g_esrc[i];
        float4 pv = *(const float4*)(qp + (size_t)s * 256 + 128 + c);
        while (1) {
            float4 pvn;
            if (i + 1 < end) {
                int sn = g_esrc[i + 1];
                pvn = *(const float4*)(qp + (size_t)sn * 256 + 128 + c);
            }
            float tx = qv.x + pv.x; tx = tx > 0.f ? tx : 0.2f * tx;
            float ty = qv.y + pv.y; ty = ty > 0.f ? ty : 0.2f * ty;
            float tz = qv.z + pv.z; tz = tz > 0.f ? tz : 0.2f * tz;
            float tw = qv.w + pv.w; tw = tw > 0.f ? tw : 0.2f * tw;
            float part = fmaf(tx, av.x, fmaf(ty, av.y, fmaf(tz, av.z, tw * av.w)));
#pragma unroll
            for (int off = 16; off > 0; off >>= 1)
                part += __shfl_xor_sync(0xffffffffu, part, off);
            float es = __expf(part);
            denom += es;
            ax = fmaf(es, pv.x, ax);
            ay = fmaf(es, pv.y, ay);
            az = fmaf(es, pv.z, az);
            aw = fmaf(es, pv.w, aw);
            i++;
            if (i >= end) break;
            pv = pvn;
        }
    }
    float inv = denom > 0.f ? 1.0f / denom : 0.f;
    float4 bv = *(const float4*)(bg + c);
    float o[4];
    o[0] = gelu_f(fmaf(ax, inv, bv.x));
    o[1] = gelu_f(fmaf(ay, inv, bv.y));
    o[2] = gelu_f(fmaf(az, inv, bv.z));
    o[3] = gelu_f(fmaf(aw, inv, bv.w));
    __half2 hh0, hh1;
    hh0.x = __float2half_rn(o[0]); hh0.y = __float2half_rn(o[1]);
    hh1.x = __float2half_rn(o[2]); hh1.y = __float2half_rn(o[3]);
    *(__half2*)(g_m2 + (size_t)gw * 128 + c) = hh0;
    *(__half2*)(g_m2 + (size_t)gw * 128 + c + 2) = hh1;
}

__global__ __launch_bounds__(256) void edge64_k(
    const float* __restrict__ qp, const float* __restrict__ a,
    const float* __restrict__ bo, float* __restrict__ out)
{
    int gw = (blockIdx.x * 256 + threadIdx.x) >> 5;
    if (gw >= NN) return;
    int lane = threadIdx.x & 31;
    int c = lane * 2;
    float2 qv = *(const float2*)(qp + (size_t)gw * 128 + c);
    float2 av = *(const float2*)(a + c);
    float ax = 0.f, ay = 0.f;
    float denom = 0.f;
    int i = g_rowptr[gw];
    int end = g_rowptr[gw + 1];
    if (i < end) {
        int s = g_esrc[i];
        float2 pv = *(const float2*)(qp + (size_t)s * 128 + 64 + c);
        while (1) {
            float2 pvn;
            if (i + 1 < end) {
                int sn = g_esrc[i + 1];
                pvn = *(const float2*)(qp + (size_t)sn * 128 + 64 + c);
            }
            float tx = qv.x + pv.x; tx = tx > 0.f ? tx : 0.2f * tx;
            float ty = qv.y + pv.y; ty = ty > 0.f ? ty : 0.2f * ty;
            float part = fmaf(tx, av.x, ty * av.y);
#pragma unroll
            for (int off = 16; off > 0; off >>= 1)
                part += __shfl_xor_sync(0xffffffffu, part, off);
            float es = __expf(part);
            denom += es;
            ax = fmaf(es, pv.x, ax);
            ay = fmaf(es, pv.y, ay);
            i++;
            if (i >= end) break;
            pv = pvn;
        }
    }
    float inv = denom > 0.f ? 1.0f / denom : 0.f;
    float2 bv = *(const float2*)(bo + c);
    float2 o;
    o.x = fmaf(ax, inv, bv.x);
    o.y = fmaf(ay, inv, bv.y);
    *(float2*)(out + (size_t)gw * 64 + c) = o;
}

// ---------------- launch ----------------
extern "C" void kernel_launch(void* const* d_in, const int* in_sizes, int n_in,
                              void* d_out, int out_size)
{
    const float* x    = (const float*)d_in[0];
    const float* W0   = (const float*)d_in[1];
    const float* b0   = (const float*)d_in[2];
    const float* Wq1  = (const float*)d_in[3];
    const float* bq1  = (const float*)d_in[4];
    const float* Wp1  = (const float*)d_in[5];
    const float* bp1  = (const float*)d_in[6];
    const float* a1   = (const float*)d_in[7];
    const float* bg2  = (const float*)d_in[8];
    const float* Wq2  = (const float*)d_in[9];
    const float* bq2  = (const float*)d_in[10];
    const float* Wp2  = (const float*)d_in[11];
    const float* bp2  = (const float*)d_in[12];
    const float* a2   = (const float*)d_in[13];
    const float* bout = (const float*)d_in[14];
    const int*   src  = (const int*)d_in[15];
    const int*   dst  = (const int*)d_in[16];
    float* out = (float*)d_out;

    __half *m2, *wqp2c;
    float *qp1, *qp2;
    cudaGetSymbolAddress((void**)&m2, g_m2);
    cudaGetSymbolAddress((void**)&wqp2c, g_wqp2c);
    cudaGetSymbolAddress((void**)&qp1, g_qp1);
    cudaGetSymbolAddress((void**)&qp2, g_qp2);

    constexpr int SMEM = 2 * ABUF;   // 69632 B
    cudaFuncSetAttribute(gemm_l1, cudaFuncAttributeMaxDynamicSharedMemorySize, SMEM);
    cudaFuncSetAttribute(gemm_mma, cudaFuncAttributeMaxDynamicSharedMemorySize, SMEM);

    // ---- fork: CSR build + layer-2 weight convert on side stream (5 launches) ----
    cudaStream_t s2;
    cudaStreamCreateWithFlags(&s2, cudaStreamNonBlocking);
    cudaEvent_t evFork, evJoin;
    cudaEventCreateWithFlags(&evFork, cudaEventDisableTiming);
    cudaEventCreateWithFlags(&evJoin, cudaEventDisableTiming);

    cudaEventRecord(evFork, 0);
    cudaStreamWaitEvent(s2, evFork, 0);
    zero_k<<<(NN + 255) / 256, 256, 0, s2>>>();
    hist_k<<<(EE + 255) / 256, 256, 0, s2>>>(dst);
    scan_k<<<1, 1024, 0, s2>>>();
    scatter_k<<<(EE + 255) / 256, 256, 0, s2>>>(src, dst);
    convw2_k<<<(128 * 128 + 255) / 256, 256, 0, s2>>>(Wq2, Wp2);
    cudaEventRecord(evJoin, s2);

    const int MB = (NN + 127) / 128;

    // ---- main chain (launch #6 = gemm_l1 -> profiled by ncu -s 5) ----
    gemm_l1<<<MB, 256, SMEM>>>(x, W0, b0, Wq1, bq1, Wp1, bp1, qp1, NN);

    cudaStreamWaitEvent(0, evJoin, 0);
    edge128_k<<<(NN * 32 + 255) / 256, 256>>>(qp1, a1, bg2);       // m2 (fp16)

    gemm_mma<<<MB, 256, SMEM>>>(m2, wqp2c, bq2, bp2, qp2, NN);
    edge64_k<<<(NN * 32 + 255) / 256, 256>>>(qp2, a2, bout, out);
}

// round 15
// speedup vs baseline: 1.0923x; 1.0923x over previous
#include <cuda_runtime.h>
#include <cuda_fp16.h>
#include <cstdint>

#define NN 50000
#define EE 800000

// ---------------- scratch (static device globals; no allocs) ----------------
__device__ __half g_m2[NN * 128];
__device__ float g_qp1[NN * 256];   // [node][0:128]=q1, [128:256]=p1
__device__ float g_qp2[NN * 128];   // [node][0:64]=q2, [64:128]=p2
__device__ __half g_w0t[128 * 128];
__device__ __half g_wqp1t[256 * 128];
__device__ __half g_wqp2t[128 * 128];
__device__ float g_bqp1[256];
__device__ float g_bqp2[128];
__device__ int   g_rowptr[NN + 1];
__device__ int   g_cursor[NN];
__device__ int   g_esrc[EE];

__device__ __forceinline__ float gelu_f(float x) {
    return 0.5f * x * (1.0f + erff(x * 0.70710678118654752440f));
}
__device__ __forceinline__ uint32_t smem_u32(const void* p) {
    uint32_t a;
    asm("{ .reg .u64 t; cvta.to.shared.u64 t, %1; cvt.u32.u64 %0, t; }" : "=r"(a) : "l"(p));
    return a;
}
__device__ __forceinline__ void ldsm4(uint32_t& r0, uint32_t& r1, uint32_t& r2, uint32_t& r3, uint32_t addr) {
    asm volatile("ldmatrix.sync.aligned.m8n8.x4.shared.b16 {%0,%1,%2,%3}, [%4];"
                 : "=r"(r0), "=r"(r1), "=r"(r2), "=r"(r3) : "r"(addr));
}
__device__ __forceinline__ void mma_f16(float* c, const uint32_t* a, const uint32_t* b) {
    asm volatile(
        "mma.sync.aligned.m16n8k16.row.col.f32.f16.f16.f32 "
        "{%0,%1,%2,%3}, {%4,%5,%6,%7}, {%8,%9}, {%0,%1,%2,%3};"
        : "+f"(c[0]), "+f"(c[1]), "+f"(c[2]), "+f"(c[3])
        : "r"(a[0]), "r"(a[1]), "r"(a[2]), "r"(a[3]), "r"(b[0]), "r"(b[1]));
}
__device__ __forceinline__ void cp16(uint32_t saddr, const void* gaddr) {
    asm volatile("cp.async.cg.shared.global [%0], [%1], 16;" :: "r"(saddr), "l"(gaddr) : "memory");
}

#define ASTRIDE 136
#define ABUF (128 * ASTRIDE * 2)   // 34816 B per buffer

// single-term fp16 mainloop: acc += A(smem) @ B(smem)^T for warp's 32x64 tile
__device__ __forceinline__ void mainloop_1t(
    uint32_t ah_base, uint32_t bh_base,
    int wm, int wn, int lane, float acc[2][8][4])
{
    const int a_r = (lane & 15);
    const int a_c = (lane >> 4) * 8;
    const int b_r = (lane & 7) + ((lane >> 4) << 3);
    const int b_c = ((lane >> 3) & 1) * 8;
#pragma unroll
    for (int ks = 0; ks < 8; ks++) {
        const int k0 = ks * 16;
        uint32_t ah[2][4];
#pragma unroll
        for (int mt = 0; mt < 2; mt++) {
            uint32_t off = (uint32_t)((wm * 32 + mt * 16 + a_r) * ASTRIDE + k0 + a_c) * 2;
            ldsm4(ah[mt][0], ah[mt][1], ah[mt][2], ah[mt][3], ah_base + off);
        }
        uint32_t bh[8][2];
#pragma unroll
        for (int ng = 0; ng < 4; ng++) {
            uint32_t off = (uint32_t)((wn * 64 + ng * 16 + b_r) * ASTRIDE + k0 + b_c) * 2;
            ldsm4(bh[2 * ng][0], bh[2 * ng][1], bh[2 * ng + 1][0], bh[2 * ng + 1][1], bh_base + off);
        }
#pragma unroll
        for (int mt = 0; mt < 2; mt++)
#pragma unroll
            for (int nt = 0; nt < 8; nt++)
                mma_f16(acc[mt][nt], ah[mt], bh[nt]);
    }
}

// ---------------- CSR build ----------------
__global__ void zero_k() {
    int i = blockIdx.x * blockDim.x + threadIdx.x;
    if (i < NN) g_cursor[i] = 0;
}
__global__ void hist_k(const int* __restrict__ dst) {
    int e = blockIdx.x * blockDim.x + threadIdx.x;
    if (e < EE) atomicAdd(&g_cursor[dst[e]], 1);
}
__global__ __launch_bounds__(1024) void scan_k() {
    __shared__ int warpsum[32];
    __shared__ int s_carry;
    __shared__ int s_tot;
    int tid = threadIdx.x, lane = tid & 31, wid = tid >> 5;
    if (tid == 0) s_carry = 0;
    __syncthreads();
    for (int base = 0; base < NN; base += 8192) {
        int idx0 = base + tid * 8;
        int v[8]; int tot = 0;
#pragma unroll
        for (int j = 0; j < 8; j++) {
            int id = idx0 + j;
            v[j] = (id < NN) ? g_cursor[id] : 0;
            tot += v[j];
        }
        int incl = tot;
#pragma unroll
        for (int off = 1; off < 32; off <<= 1) {
            int t = __shfl_up_sync(0xffffffffu, incl, off);
            if (lane >= off) incl += t;
        }
        if (lane == 31) warpsum[wid] = incl;
        __syncthreads();
        if (wid == 0) {
            int w = warpsum[lane];
            int wi = w;
#pragma unroll
            for (int off = 1; off < 32; off <<= 1) {
                int t = __shfl_up_sync(0xffffffffu, wi, off);
                if (lane >= off) wi += t;
            }
            warpsum[lane] = wi - w;
            if (lane == 31) s_tot = wi;
        }
        __syncthreads();
        int run = s_carry + warpsum[wid] + (incl - tot);
#pragma unroll
        for (int j = 0; j < 8; j++) {
            int id = idx0 + j;
            if (id < NN) { g_rowptr[id] = run; g_cursor[id] = 0; }
            run += v[j];
        }
        __syncthreads();
        if (tid == 0) s_carry += s_tot;
        __syncthreads();
    }
    if (threadIdx.x == 0) g_rowptr[NN] = s_carry;
}
__global__ void scatter_k(const int* __restrict__ src, const int* __restrict__ dst) {
    int e = blockIdx.x * blockDim.x + threadIdx.x;
    if (e < EE) {
        int d = dst[e];
        int pos = g_rowptr[d] + atomicAdd(&g_cursor[d], 1);
        g_esrc[pos] = src[e];
    }
}

// ---------------- conversions ----------------
__global__ void convw_k(const float* __restrict__ Wa, const float* __restrict__ Wb,
                        const float* __restrict__ ba, const float* __restrict__ bb,
                        __half* __restrict__ Wt, float* __restrict__ bc, int na, int nb) {
    int nc = na + nb;
    int i = blockIdx.x * blockDim.x + threadIdx.x;
    if (i < nc * 128) {
        int n = i >> 7, k = i & 127;
        float v = (n < na) ? Wa[(size_t)k * na + n] : Wb[(size_t)k * nb + (n - na)];
        Wt[i] = __float2half_rn(v);
    }
    if (bc && i < nc) bc[i] = (i < na) ? ba[i] : bb[i - na];
}

// ---------------- fused layer-1: qp1 = gelu(x@W0+b0) @ Wqp1 + bqp1 -----------
// Triple-buffered weights: W0->B0 and Wq1->B1 issued at entry; Wp1->B0 issued
// right after mainloop-1. All staging latency hidden behind compute.
__global__ __launch_bounds__(256, 2) void gemm_l1(
    const float* __restrict__ x, const __half* __restrict__ W0t,
    const float* __restrict__ b0, const __half* __restrict__ Wqp1t,
    const float* __restrict__ bqp1, float* __restrict__ qp1, int M)
{
    extern __shared__ char sm[];
    char* AH = sm;
    char* B0 = sm + ABUF;
    char* B1 = sm + 2 * ABUF;

    const int tid = threadIdx.x;
    const int warp = tid >> 5, lane = tid & 31;
    const int wm = warp >> 1, wn = warp & 1;
    const int rowBase = blockIdx.x * 128;

    const uint32_t ah_base = smem_u32(AH);
    const uint32_t b0_base = smem_u32(B0);
    const uint32_t b1_base = smem_u32(B1);

    // ---- issue W0 -> B0 (group 0) and Wq1-half -> B1 (group 1) ----
#pragma unroll
    for (int it = 0; it < 8; it++) {
        int idx = tid + it * 256;               // 0..2047
        int row = idx >> 4, ch = idx & 15;
        uint32_t so = (uint32_t)(row * ASTRIDE + ch * 8) * 2;
        cp16(b0_base + so, W0t + (size_t)row * 128 + ch * 8);
    }
    asm volatile("cp.async.commit_group;" ::: "memory");
#pragma unroll
    for (int it = 0; it < 8; it++) {
        int idx = tid + it * 256;
        int row = idx >> 4, ch = idx & 15;
        uint32_t so = (uint32_t)(row * ASTRIDE + ch * 8) * 2;
        cp16(b1_base + so, Wqp1t + (size_t)row * 128 + ch * 8);
    }
    asm volatile("cp.async.commit_group;" ::: "memory");

    // ---- stage x (fp32 -> fp16 in regs) into AH ----
#pragma unroll
    for (int it = 0; it < 8; it++) {
        int idx = tid + it * 256;
        int row = idx >> 4, ch = idx & 15;
        int gr = rowBase + row; if (gr >= M) gr = M - 1;
        float4 v0 = *(const float4*)(x + (size_t)gr * 128 + ch * 8);
        float4 v1 = *(const float4*)(x + (size_t)gr * 128 + ch * 8 + 4);
        __half hh[8];
        hh[0] = __float2half_rn(v0.x); hh[1] = __float2half_rn(v0.y);
        hh[2] = __float2half_rn(v0.z); hh[3] = __float2half_rn(v0.w);
        hh[4] = __float2half_rn(v1.x); hh[5] = __float2half_rn(v1.y);
        hh[6] = __float2half_rn(v1.z); hh[7] = __float2half_rn(v1.w);
        uint32_t so = (uint32_t)(row * ASTRIDE + ch * 8) * 2;
        *(uint4*)(AH + so) = *(const uint4*)hh;
    }
    asm volatile("cp.async.wait_group 1;" ::: "memory");   // W0 ready
    __syncthreads();

    float acc[2][8][4];
#pragma unroll
    for (int i = 0; i < 2; i++)
#pragma unroll
        for (int j = 0; j < 8; j++)
#pragma unroll
            for (int k = 0; k < 4; k++) acc[i][j][k] = 0.f;

    // ---- mainloop 1: m1 = x @ W0^T (B0) ----
    mainloop_1t(ah_base, b0_base, wm, wn, lane, acc);
    __syncthreads();   // all done reading AH + B0

    // ---- issue Wp1-half -> B0 (group 2), hidden under epilogue-1 + cb0 ----
#pragma unroll
    for (int it = 0; it < 8; it++) {
        int idx = tid + it * 256;
        int row = idx >> 4, ch = idx & 15;
        uint32_t so = (uint32_t)(row * ASTRIDE + ch * 8) * 2;
        cp16(b0_base + so, Wqp1t + (size_t)(128 + row) * 128 + ch * 8);
    }
    asm volatile("cp.async.commit_group;" ::: "memory");

    // ---- epilogue 1: gelu(m1+b0) -> fp16 back into AH ----
#pragma unroll
    for (int mt = 0; mt < 2; mt++)
#pragma unroll
        for (int nt = 0; nt < 8; nt++) {
            int c = wn * 64 + nt * 8 + (lane & 3) * 2;
            float bb0 = b0[c], bb1 = b0[c + 1];
#pragma unroll
            for (int h = 0; h < 2; h++) {
                int r = wm * 32 + mt * 16 + (lane >> 2) + h * 8;
                float v0 = gelu_f(acc[mt][nt][2 * h + 0] + bb0);
                float v1 = gelu_f(acc[mt][nt][2 * h + 1] + bb1);
                uint32_t so = (uint32_t)(r * ASTRIDE + c) * 2;
                __half2 hh;
                hh.x = __float2half_rn(v0);
                hh.y = __float2half_rn(v1);
                *(__half2*)(AH + so) = hh;
            }
        }
    asm volatile("cp.async.wait_group 1;" ::: "memory");   // Wq1 ready
    __syncthreads();

    // ---- cb0: qp1 cols [0:128) = m1 @ Wq1^T (B1) ----
#pragma unroll
    for (int i = 0; i < 2; i++)
#pragma unroll
        for (int j = 0; j < 8; j++)
#pragma unroll
            for (int k = 0; k < 4; k++) acc[i][j][k] = 0.f;
    mainloop_1t(ah_base, b1_base, wm, wn, lane, acc);

#pragma unroll
    for (int mt = 0; mt < 2; mt++)
#pragma unroll
        for (int nt = 0; nt < 8; nt++) {
            int c = wn * 64 + nt * 8 + (lane & 3) * 2;
            float bb0 = bqp1[c], bb1 = bqp1[c + 1];
#pragma unroll
            for (int h = 0; h < 2; h++) {
                int r = rowBase + wm * 32 + mt * 16 + (lane >> 2) + h * 8;
                if (r < M) {
                    float v0 = acc[mt][nt][2 * h + 0] + bb0;
                    float v1 = acc[mt][nt][2 * h + 1] + bb1;
                    *(float2*)(qp1 + (size_t)r * 256 + c) = make_float2(v0, v1);
                }
            }
        }
    asm volatile("cp.async.wait_group 0;" ::: "memory");   // Wp1 ready
    __syncthreads();

    // ---- cb1: qp1 cols [128:256) = m1 @ Wp1^T (B0) ----
#pragma unroll
    for (int i = 0; i < 2; i++)
#pragma unroll
        for (int j = 0; j < 8; j++)
#pragma unroll
            for (int k = 0; k < 4; k++) acc[i][j][k] = 0.f;
    mainloop_1t(ah_base, b0_base, wm, wn, lane, acc);

#pragma unroll
    for (int mt = 0; mt < 2; mt++)
#pragma unroll
        for (int nt = 0; nt < 8; nt++) {
            int c = 128 + wn * 64 + nt * 8 + (lane & 3) * 2;
            float bb0 = bqp1[c], bb1 = bqp1[c + 1];
#pragma unroll
            for (int h = 0; h < 2; h++) {
                int r = rowBase + wm * 32 + mt * 16 + (lane >> 2) + h * 8;
                if (r < M) {
                    float v0 = acc[mt][nt][2 * h + 0] + bb0;
                    float v1 = acc[mt][nt][2 * h + 1] + bb1;
                    *(float2*)(qp1 + (size_t)r * 256 + c) = make_float2(v0, v1);
                }
            }
        }
}

// ---------------- layer-2 GEMM: qp2 = m2(fp16) @ Wqp2^T + bqp2 ---------------
__global__ __launch_bounds__(256, 2) void gemm_mma(
    const __half* __restrict__ A, const __half* __restrict__ Bh,
    const float* __restrict__ bias, float* __restrict__ Cf, int M, int ncols)
{
    extern __shared__ char sm[];
    char* AH = sm;
    char* BH = sm + ABUF;

    const int tid = threadIdx.x;
    const int warp = tid >> 5, lane = tid & 31;
    const int wm = warp >> 1, wn = warp & 1;
    const int rowBase = blockIdx.x * 128;

    const uint32_t ah_base = smem_u32(AH);
    const uint32_t bh_base = smem_u32(BH);

#pragma unroll
    for (int it = 0; it < 8; it++) {
        int idx = tid + it * 256;
        int row = idx >> 4, ch = idx & 15;
        int gr = rowBase + row; if (gr >= M) gr = M - 1;
        uint32_t so = (uint32_t)(row * ASTRIDE + ch * 8) * 2;
        cp16(ah_base + so, A + (size_t)gr * 128 + ch * 8);
        cp16(bh_base + so, Bh + (size_t)row * 128 + ch * 8);
    }
    asm volatile("cp.async.commit_group;" ::: "memory");
    asm volatile("cp.async.wait_group 0;" ::: "memory");
    __syncthreads();

    float acc[2][8][4];
#pragma unroll
    for (int i = 0; i < 2; i++)
#pragma unroll
        for (int j = 0; j < 8; j++)
#pragma unroll
            for (int k = 0; k < 4; k++) acc[i][j][k] = 0.f;
    mainloop_1t(ah_base, bh_base, wm, wn, lane, acc);

#pragma unroll
    for (int mt = 0; mt < 2; mt++)
#pragma unroll
        for (int nt = 0; nt < 8; nt++) {
            int c = wn * 64 + nt * 8 + (lane & 3) * 2;
            float b0 = bias[c], b1 = bias[c + 1];
#pragma unroll
            for (int h = 0; h < 2; h++) {
                int r = rowBase + wm * 32 + mt * 16 + (lane >> 2) + h * 8;
                if (r < M) {
                    float v0 = acc[mt][nt][2 * h + 0] + b0;
                    float v1 = acc[mt][nt][2 * h + 1] + b1;
                    *(float2*)(Cf + (size_t)r * ncols + c) = make_float2(v0, v1);
                }
            }
        }
}

// ---------------- edge kernels: one warp per dst node (R8 formulation) --------
__global__ __launch_bounds__(256) void edge128_k(
    const float* __restrict__ qp, const float* __restrict__ a,
    const float* __restrict__ bg)
{
    int gw = (blockIdx.x * 256 + threadIdx.x) >> 5;
    if (gw >= NN) return;
    int lane = threadIdx.x & 31;
    int c = lane * 4;
    float4 qv = *(const float4*)(qp + (size_t)gw * 256 + c);
    float4 av = *(const float4*)(a + c);
    float ax = 0.f, ay = 0.f, az = 0.f, aw = 0.f;
    float denom = 0.f;
    int i = g_rowptr[gw];
    int end = g_rowptr[gw + 1];
    if (i < end) {
        int s = g_esrc[i];
        float4 pv = *(const float4*)(qp + (size_t)s * 256 + 128 + c);
        while (1) {
            float4 pvn;
            if (i + 1 < end) {
                int sn = g_esrc[i + 1];
                pvn = *(const float4*)(qp + (size_t)sn * 256 + 128 + c);
            }
            float tx = qv.x + pv.x; tx = tx > 0.f ? tx : 0.2f * tx;
            float ty = qv.y + pv.y; ty = ty > 0.f ? ty : 0.2f * ty;
            float tz = qv.z + pv.z; tz = tz > 0.f ? tz : 0.2f * tz;
            float tw = qv.w + pv.w; tw = tw > 0.f ? tw : 0.2f * tw;
            float part = fmaf(tx, av.x, fmaf(ty, av.y, fmaf(tz, av.z, tw * av.w)));
#pragma unroll
            for (int off = 16; off > 0; off >>= 1)
                part += __shfl_xor_sync(0xffffffffu, part, off);
            float es = __expf(part);
            denom += es;
            ax = fmaf(es, pv.x, ax);
            ay = fmaf(es, pv.y, ay);
            az = fmaf(es, pv.z, az);
            aw = fmaf(es, pv.w, aw);
            i++;
            if (i >= end) break;
            pv = pvn;
        }
    }
    float inv = denom > 0.f ? 1.0f / denom : 0.f;
    float4 bv = *(const float4*)(bg + c);
    float o[4];
    o[0] = gelu_f(fmaf(ax, inv, bv.x));
    o[1] = gelu_f(fmaf(ay, inv, bv.y));
    o[2] = gelu_f(fmaf(az, inv, bv.z));
    o[3] = gelu_f(fmaf(aw, inv, bv.w));
    __half2 hh0, hh1;
    hh0.x = __float2half_rn(o[0]); hh0.y = __float2half_rn(o[1]);
    hh1.x = __float2half_rn(o[2]); hh1.y = __float2half_rn(o[3]);
    *(__half2*)(g_m2 + (size_t)gw * 128 + c) = hh0;
    *(__half2*)(g_m2 + (size_t)gw * 128 + c + 2) = hh1;
}

__global__ __launch_bounds__(256) void edge64_k(
    const float* __restrict__ qp, const float* __restrict__ a,
    const float* __restrict__ bo, float* __restrict__ out)
{
    int gw = (blockIdx.x * 256 + threadIdx.x) >> 5;
    if (gw >= NN) return;
    int lane = threadIdx.x & 31;
    int c = lane * 2;
    float2 qv = *(const float2*)(qp + (size_t)gw * 128 + c);
    float2 av = *(const float2*)(a + c);
    float ax = 0.f, ay = 0.f;
    float denom = 0.f;
    int i = g_rowptr[gw];
    int end = g_rowptr[gw + 1];
    if (i < end) {
        int s = g_esrc[i];
        float2 pv = *(const float2*)(qp + (size_t)s * 128 + 64 + c);
        while (1) {
            float2 pvn;
            if (i + 1 < end) {
                int sn = g_esrc[i + 1];
                pvn = *(const float2*)(qp + (size_t)sn * 128 + 64 + c);
            }
            float tx = qv.x + pv.x; tx = tx > 0.f ? tx : 0.2f * tx;
            float ty = qv.y + pv.y; ty = ty > 0.f ? ty : 0.2f * ty;
            float part = fmaf(tx, av.x, ty * av.y);
#pragma unroll
            for (int off = 16; off > 0; off >>= 1)
                part += __shfl_xor_sync(0xffffffffu, part, off);
            float es = __expf(part);
            denom += es;
            ax = fmaf(es, pv.x, ax);
            ay = fmaf(es, pv.y, ay);
            i++;
            if (i >= end) break;
            pv = pvn;
        }
    }
    float inv = denom > 0.f ? 1.0f / denom : 0.f;
    float2 bv = *(const float2*)(bo + c);
    float2 o;
    o.x = fmaf(ax, inv, bv.x);
    o.y = fmaf(ay, inv, bv.y);
    *(float2*)(out + (size_t)gw * 64 + c) = o;
}

// ---------------- launch ----------------
extern "C" void kernel_launch(void* const* d_in, const int* in_sizes, int n_in,
                              void* d_out, int out_size)
{
    const float* x    = (const float*)d_in[0];
    const float* W0   = (const float*)d_in[1];
    const float* b0   = (const float*)d_in[2];
    const float* Wq1  = (const float*)d_in[3];
    const float* bq1  = (const float*)d_in[4];
    const float* Wp1  = (const float*)d_in[5];
    const float* bp1  = (const float*)d_in[6];
    const float* a1   = (const float*)d_in[7];
    const float* bg2  = (const float*)d_in[8];
    const float* Wq2  = (const float*)d_in[9];
    const float* bq2  = (const float*)d_in[10];
    const float* Wp2  = (const float*)d_in[11];
    const float* bp2  = (const float*)d_in[12];
    const float* a2   = (const float*)d_in[13];
    const float* bout = (const float*)d_in[14];
    const int*   src  = (const int*)d_in[15];
    const int*   dst  = (const int*)d_in[16];
    float* out = (float*)d_out;

    __half *m2, *w0t, *wqp1t, *wqp2t;
    float *qp1, *qp2, *bqp1, *bqp2;
    cudaGetSymbolAddress((void**)&m2, g_m2);
    cudaGetSymbolAddress((void**)&w0t, g_w0t);
    cudaGetSymbolAddress((void**)&wqp1t, g_wqp1t);
    cudaGetSymbolAddress((void**)&wqp2t, g_wqp2t);
    cudaGetSymbolAddress((void**)&qp1, g_qp1); cudaGetSymbolAddress((void**)&qp2, g_qp2);
    cudaGetSymbolAddress((void**)&bqp1, g_bqp1); cudaGetSymbolAddress((void**)&bqp2, g_bqp2);

    constexpr int SMEM_L1 = 3 * ABUF;   // 104448 B
    constexpr int SMEM_L2 = 2 * ABUF;   // 69632 B
    cudaFuncSetAttribute(gemm_l1, cudaFuncAttributeMaxDynamicSharedMemorySize, SMEM_L1);
    cudaFuncSetAttribute(gemm_mma, cudaFuncAttributeMaxDynamicSharedMemorySize, SMEM_L2);

    // ---- fork: CSR build + layer-2 weight conversion on side stream ----
    cudaStream_t s2;
    cudaStreamCreateWithFlags(&s2, cudaStreamNonBlocking);
    cudaEvent_t evFork, evJoin;
    cudaEventCreateWithFlags(&evFork, cudaEventDisableTiming);
    cudaEventCreateWithFlags(&evJoin, cudaEventDisableTiming);

    cudaEventRecord(evFork, 0);
    cudaStreamWaitEvent(s2, evFork, 0);
    zero_k<<<(NN + 255) / 256, 256, 0, s2>>>();
    hist_k<<<(EE + 255) / 256, 256, 0, s2>>>(dst);
    scan_k<<<1, 1024, 0, s2>>>();
    scatter_k<<<(EE + 255) / 256, 256, 0, s2>>>(src, dst);
    convw_k<<<(128 * 128 + 255) / 256, 256, 0, s2>>>(Wq2, Wp2, bq2, bp2, wqp2t, bqp2, 64, 64);
    cudaEventRecord(evJoin, s2);

    // ---- main chain ----
    convw_k<<<(128 * 128 + 255) / 256, 256>>>(W0, W0, b0, b0, w0t, nullptr, 128, 0);
    convw_k<<<(256 * 128 + 255) / 256, 256>>>(Wq1, Wp1, bq1, bp1, wqp1t, bqp1, 128, 128);

    const int MB = (NN + 127) / 128;

    gemm_l1<<<MB, 256, SMEM_L1>>>(x, w0t, b0, wqp1t, bqp1, qp1, NN);

    // join: edge pass needs the CSR
    cudaStreamWaitEvent(0, evJoin, 0);
    edge128_k<<<(NN * 32 + 255) / 256, 256>>>(qp1, a1, bg2);       // m2 (fp16)

    gemm_mma<<<MB, 256, SMEM_L2>>>(m2, wqp2t, bqp2, qp2, NN, 128);
    edge64_k<<<(NN * 32 + 255) / 256, 256>>>(qp2, a2, bout, out);
}